// round 14
// baseline (speedup 1.0000x reference)
#include <cuda_runtime.h>
#include <cstdint>
#include <math.h>

#define TT 2048
#define BB 32
#define DD 512
#define HH 512
#define GG 2048        // 4*H
#define NCTA 128       // persistent CTAs (one wave)
#define RTHREADS 512   // 16 warps
#define NW 16
#define KSL 32         // k-slice per warp
#define HSTR 520       // hS row stride (floats): rows 16B-aligned, adjacent rows +32B mod 128
#define GP 35          // gred b-stride pad

// ---------------- device scratch (static, no allocs) ----------------
__device__ __align__(16) float g_hbuf[2][BB * HH];            // ping-pong h, [b][k]
__device__ __align__(128) unsigned g_flags[NCTA * 32];        // 1 flag/CTA, own 128B line

// ---------------- packed fp32x2 helpers ----------------
__device__ __forceinline__ unsigned long long pk2(float lo, float hi) {
    unsigned long long r;
    asm("mov.b64 %0, {%1, %2};" : "=l"(r) : "f"(lo), "f"(hi));
    return r;
}
__device__ __forceinline__ void upk2(unsigned long long v, float& lo, float& hi) {
    asm("mov.b64 {%0, %1}, %2;" : "=f"(lo), "=f"(hi) : "l"(v));
}
__device__ __forceinline__ void ffma2(unsigned long long& acc, unsigned long long a,
                                      unsigned long long b) {
    asm("fma.rn.f32x2 %0, %1, %2, %0;" : "+l"(acc) : "l"(a), "l"(b));
}
__device__ __forceinline__ void ldg_cg_2u64(const void* p, unsigned long long& a,
                                            unsigned long long& b) {
    asm volatile("ld.global.cg.v2.u64 {%0, %1}, [%2];" : "=l"(a), "=l"(b) : "l"(p));
}
__device__ __forceinline__ float sigmoid_f(float x) {
    return __fdividef(1.f, 1.f + __expf(-x));
}
__device__ __forceinline__ float tanh_f(float x) {
    return 2.f * __fdividef(1.f, 1.f + __expf(-2.f * x)) - 1.f;
}

// =====================================================================
// Single persistent kernel: x-GEMM fused into the recurrence.
//   gates(t) = x[t]·W_ih^T + h(t)·W_hh^T + b_ih + b_hh
//   Lane map (both GEMMs): rh = lane>>2 (rows 2rh, 2rh+1),
//   bq = lane&3 (batches 4j+bq, j=0..7). Warp w owns k in [32w, 32w+32).
//   W_hh: 32 persistent f32x2 regs/lane.  W_ih: packed SMEM [w][kp][r].
//   x read from L2 (no dependency; runs while producers finish).
//   h staged per-warp into hS (stride 520 -> 64B/wf GEMM LDS).
//   Flag protocol identical to R12 (per-warp producer waits, window {t,t+1}).
// =====================================================================
struct __align__(16) SmemR {
    float  hS[BB * HSTR];        // staged h, [b][k]               66560 B
    float2 w2ih[NW * 16 * 16];   // [w][kp][r]: {wih[r][k], wih[r][k+1]}  32768 B
    float  gred[NW][16][GP];     // [w][row][b(padded)]            35840 B
};

__global__ __launch_bounds__(RTHREADS, 1) void lstm_fused(
    const float* __restrict__ x, const float* __restrict__ h0,
    const float* __restrict__ c0, const float* __restrict__ w_ih,
    const float* __restrict__ w_hh, const float* __restrict__ b_ih,
    const float* __restrict__ b_hh,
    float* __restrict__ out, int write_state) {
    extern __shared__ char smem_raw[];
    SmemR* s = (SmemR*)smem_raw;

    const int tid = threadIdx.x;
    const int w = tid >> 5, lane = tid & 31;
    const int cid = blockIdx.x;
    const int j0 = cid * 4;

    // ---- GEMM mapping: 2 rows x 8 batches x 32-k slice per lane ----
    const int rh = lane >> 2, bq = lane & 3;
    const int r0 = 2 * rh, r1 = r0 + 1;                      // CTA-local rows
    const int R0 = (r0 >> 2) * HH + j0 + (r0 & 3);           // global rows
    const int R1 = (r1 >> 2) * HH + j0 + (r1 & 3);

    // ---- persistent W_hh registers (loaded once for all 2048 steps) ----
    unsigned long long wA[16], wB[16];
#pragma unroll
    for (int m = 0; m < 8; m++) {
        float4 a = *(const float4*)&w_hh[(size_t)R0 * HH + w * KSL + 4 * m];
        wA[2 * m] = pk2(a.x, a.y); wA[2 * m + 1] = pk2(a.z, a.w);
        float4 b = *(const float4*)&w_hh[(size_t)R1 * HH + w * KSL + 4 * m];
        wB[2 * m] = pk2(b.x, b.y); wB[2 * m + 1] = pk2(b.z, b.w);
    }

    // ---- pack W_ih into SMEM once: w2ih[w][kp][r] (k = 32w + 2kp) ----
    for (int idx = tid; idx < NW * 16 * 16; idx += RTHREADS) {
        int ww = idx >> 8;
        int kp = (idx >> 4) & 15;
        int r  = idx & 15;
        int row = (r >> 2) * HH + j0 + (r & 3);
        int k = ww * KSL + kp * 2;
        s->w2ih[idx] = make_float2(w_ih[(size_t)row * DD + k],
                                   w_ih[(size_t)row * DD + k + 1]);
    }

    // ---- staging mapping ----
    const int sc = lane & 7, srg = lane >> 3;

    // ---- reduce mapping: thread owns gate element (q, cc, bb) ----
    const int cc = w >> 2, bh8 = w & 3;
    const int q = lane >> 3, b8 = lane & 7;
    const int bb = bh8 * 8 + b8;
    const float bhb = b_ih[q * HH + j0 + cc] + b_hh[q * HH + j0 + cc];
    float cs = 0.f;
    if (q == 0) cs = c0[(size_t)bb * HH + j0 + cc];
    float h_keep = 0.f, c_keep = 0.f;
    __syncthreads();   // w2ih visible

    for (int t = 0; t < TT; t++) {
        // ======== x-GEMM (no recurrence dependency; producers keep running) ====
        unsigned long long accA[8], accB[8];
#pragma unroll
        for (int j = 0; j < 8; j++) { accA[j] = 0ull; accB[j] = 0ull; }
        {
            const float* xb = x + (size_t)t * BB * DD;
#pragma unroll
            for (int m = 0; m < 8; m++) {
                // W_ih for kp = 2m, 2m+1; rows r0,r1 (16B, 8-distinct -> 1 wf)
                ulonglong2 w0 = *(const ulonglong2*)&s->w2ih[w * 256 + (2 * m) * 16 + r0];
                ulonglong2 w1 = *(const ulonglong2*)&s->w2ih[w * 256 + (2 * m + 1) * 16 + r0];
#pragma unroll
                for (int j = 0; j < 8; j++) {
                    unsigned long long hx, hy;
                    ldg_cg_2u64(xb + (size_t)(4 * j + bq) * DD + w * KSL + 4 * m, hx, hy);
                    ffma2(accA[j], hx, w0.x);
                    ffma2(accB[j], hx, w0.y);
                    ffma2(accA[j], hy, w1.x);
                    ffma2(accB[j], hy, w1.y);
                }
            }
        }

        // ======== per-warp producer wait (R12 protocol, window {t, t+1}) ======
        if (t > 0) {
            if (lane < 8) {
                const unsigned* fp = &g_flags[(w * 8 + lane) * 32];
                unsigned want = (unsigned)t, v;
                do {
                    asm volatile("ld.acquire.gpu.u32 %0, [%1];"
                                 : "=r"(v) : "l"(fp) : "memory");
                } while (v - want > 1u);
            }
            __syncwarp();
        }

        // ======== per-warp stage: own 32-k slice of h for all 32 batches ======
        const float* hsrc = (t == 0) ? h0 : g_hbuf[t & 1];   // [b][k]
#pragma unroll
        for (int i = 0; i < 8; i++) {
            int b = srg + 4 * i;
            float4 v = __ldcg((const float4*)(hsrc + (size_t)b * HH + w * KSL) + sc);
            *(float4*)&s->hS[b * HSTR + w * KSL + 4 * sc] = v;
        }
        __syncwarp();

        // ======== h-GEMM: acc += h · W_hh (weights in registers) =============
#pragma unroll
        for (int j = 0; j < 8; j++) {
            const ulonglong2* hp =
                (const ulonglong2*)&s->hS[(4 * j + bq) * HSTR + w * KSL];
            unsigned long long a0 = accA[j], a1 = accB[j];
#pragma unroll
            for (int m = 0; m < 8; m++) {
                ulonglong2 hv = hp[m];               // k-pairs 2m, 2m+1
                ffma2(a0, hv.x, wA[2 * m]);
                ffma2(a1, hv.x, wB[2 * m]);
                ffma2(a0, hv.y, wA[2 * m + 1]);
                ffma2(a1, hv.y, wB[2 * m + 1]);
            }
            accA[j] = a0; accB[j] = a1;
        }

        // ======== fold k-parity, publish partials ============================
#pragma unroll
        for (int j = 0; j < 8; j++) {
            float lo, hi;
            upk2(accA[j], lo, hi);
            s->gred[w][r0][4 * j + bq] = lo + hi;
            upk2(accB[j], lo, hi);
            s->gred[w][r1][4 * j + bq] = lo + hi;
        }
        __syncthreads();

        // ======== distributed reduce + gates =================================
        float gate = bhb;
#pragma unroll
        for (int ww = 0; ww < NW; ww++)
            gate += s->gred[ww][q * 4 + cc][bb];
        float act = (q == 2) ? tanh_f(gate) : sigmoid_f(gate);
        float a1 = __shfl_xor_sync(0xffffffffu, act, 8);    // q^1
        float a2 = __shfl_xor_sync(0xffffffffu, act, 16);   // q^2
        float a3 = __shfl_xor_sync(0xffffffffu, a1, 16);    // q^3
        float hn = 0.f;
        if (q == 0) {
            float iv = act, fv = a1, gv = a2, ov = a3;
            float cn = fv * cs + iv * gv;
            hn = ov * tanh_f(cn);
            cs = cn;
            g_hbuf[(t + 1) & 1][(size_t)bb * HH + j0 + cc] = hn;
            h_keep = hn; c_keep = cn;
        }
        __syncthreads();   // all h writes + gred reads complete

        // ======== release own flag; out[t] store off the critical path =======
        if (tid == 0) {
            asm volatile("st.release.gpu.u32 [%0], %1;"
                         :: "l"(&g_flags[cid * 32]), "r"((unsigned)(t + 1))
                         : "memory");
        }
        if (q == 0)
            out[(size_t)t * BB * HH + (size_t)bb * HH + j0 + cc] = hn;
    }

    if (write_state && q == 0) {
        out[(size_t)TT * BB * HH + (size_t)bb * HH + j0 + cc] = h_keep;
        out[(size_t)TT * BB * HH + (size_t)BB * HH + (size_t)bb * HH + j0 + cc] = c_keep;
    }
}

// =====================================================================
// launch — single fused kernel, no pre-pass, no 512MB scratch
// =====================================================================
extern "C" void kernel_launch(void* const* d_in, const int* in_sizes, int n_in,
                              void* d_out, int out_size) {
    const float* x    = (const float*)d_in[0];
    const float* h0   = (const float*)d_in[1];
    const float* c0   = (const float*)d_in[2];
    const float* w_ih = (const float*)d_in[3];
    const float* w_hh = (const float*)d_in[4];
    const float* b_ih = (const float*)d_in[5];
    const float* b_hh = (const float*)d_in[6];
    float* out = (float*)d_out;

    int smem = (int)sizeof(SmemR);
    cudaFuncSetAttribute(lstm_fused, cudaFuncAttributeMaxDynamicSharedMemorySize, smem);
    int write_state = (out_size >= TT * BB * HH + 2 * BB * HH) ? 1 : 0;
    lstm_fused<<<NCTA, RTHREADS, smem>>>(x, h0, c0, w_ih, w_hh, b_ih, b_hh,
                                         out, write_state);
}

// round 15
// speedup vs baseline: 1.8701x; 1.8701x over previous
#include <cuda_runtime.h>
#include <cstdint>
#include <math.h>

#define TT 2048
#define BB 32
#define DD 512
#define HH 512
#define GG 2048        // 4*H
#define NCTA 128       // persistent CTAs (one wave)
#define RTHREADS 512   // 16 warps
#define NW 16
#define KSL 32         // k-slice per warp
#define HSTR 520       // hS/xS row stride (floats): rows 16B-aligned, +32B mod 128 per row
#define GP 35          // gred b-stride pad

// ---------------- device scratch (static, no allocs) ----------------
__device__ __align__(16) float g_hbuf[2][BB * HH];            // ping-pong h, [b][k]
__device__ __align__(128) unsigned g_flags[NCTA * 32];        // 1 flag/CTA, own 128B line

// ---------------- packed fp32x2 helpers ----------------
__device__ __forceinline__ unsigned long long pk2(float lo, float hi) {
    unsigned long long r;
    asm("mov.b64 %0, {%1, %2};" : "=l"(r) : "f"(lo), "f"(hi));
    return r;
}
__device__ __forceinline__ void upk2(unsigned long long v, float& lo, float& hi) {
    asm("mov.b64 {%0, %1}, %2;" : "=f"(lo), "=f"(hi) : "l"(v));
}
__device__ __forceinline__ void ffma2(unsigned long long& acc, unsigned long long a,
                                      unsigned long long b) {
    asm("fma.rn.f32x2 %0, %1, %2, %0;" : "+l"(acc) : "l"(a), "l"(b));
}
__device__ __forceinline__ float sigmoid_f(float x) {
    return __fdividef(1.f, 1.f + __expf(-x));
}
__device__ __forceinline__ float tanh_f(float x) {
    return 2.f * __fdividef(1.f, 1.f + __expf(-2.f * x)) - 1.f;
}

// =====================================================================
// Single persistent kernel, x software-pipelined through SMEM.
//   gates(t) = x[t]·W_ih^T + h(t)·W_hh^T + b_ih + b_hh
//   Warp w owns k in [32w, 32w+32) of BOTH x and h -> xS slice is
//   per-warp private: consume x[t] from xS, then prefetch x[t+1] into
//   the same slice (__syncwarp only). DRAM latency hidden by one step.
//   Lane map (all GEMMs): rh = lane>>2 (rows 2rh, 2rh+1), bq = lane&3
//   (batches 4j+bq). W_hh: 32 persistent f32x2 regs. W_ih: packed SMEM.
//   Flag protocol identical to R12 (per-warp producer waits, {t, t+1}).
// =====================================================================
struct __align__(16) SmemR {
    float  hS[BB * HSTR];        // staged h, [b][k]                66560 B
    float  xS[BB * HSTR];        // pipelined x[t], [b][k]          66560 B
    float2 w2ih[NW * 16 * 16];   // [w][kp][r]: {wih[r][k], wih[r][k+1]}  32768 B
    float  gred[NW][16][GP];     // [w][row][b(padded)]             35840 B
};                               // total 201728 B

__global__ __launch_bounds__(RTHREADS, 1) void lstm_fused(
    const float* __restrict__ x, const float* __restrict__ h0,
    const float* __restrict__ c0, const float* __restrict__ w_ih,
    const float* __restrict__ w_hh, const float* __restrict__ b_ih,
    const float* __restrict__ b_hh,
    float* __restrict__ out, int write_state) {
    extern __shared__ char smem_raw[];
    SmemR* s = (SmemR*)smem_raw;

    const int tid = threadIdx.x;
    const int w = tid >> 5, lane = tid & 31;
    const int cid = blockIdx.x;
    const int j0 = cid * 4;

    // ---- GEMM mapping: 2 rows x 8 batches x 32-k slice per lane ----
    const int rh = lane >> 2, bq = lane & 3;
    const int r0 = 2 * rh, r1 = r0 + 1;                      // CTA-local rows
    const int R0 = (r0 >> 2) * HH + j0 + (r0 & 3);           // global rows
    const int R1 = (r1 >> 2) * HH + j0 + (r1 & 3);

    // ---- persistent W_hh registers (loaded once for all 2048 steps) ----
    unsigned long long wA[16], wB[16];
#pragma unroll
    for (int m = 0; m < 8; m++) {
        float4 a = *(const float4*)&w_hh[(size_t)R0 * HH + w * KSL + 4 * m];
        wA[2 * m] = pk2(a.x, a.y); wA[2 * m + 1] = pk2(a.z, a.w);
        float4 b = *(const float4*)&w_hh[(size_t)R1 * HH + w * KSL + 4 * m];
        wB[2 * m] = pk2(b.x, b.y); wB[2 * m + 1] = pk2(b.z, b.w);
    }

    // ---- pack W_ih into SMEM once: w2ih[w][kp][r] (k = 32w + 2kp) ----
    for (int idx = tid; idx < NW * 16 * 16; idx += RTHREADS) {
        int ww = idx >> 8;
        int kp = (idx >> 4) & 15;
        int r  = idx & 15;
        int row = (r >> 2) * HH + j0 + (r & 3);
        int k = ww * KSL + kp * 2;
        s->w2ih[idx] = make_float2(w_ih[(size_t)row * DD + k],
                                   w_ih[(size_t)row * DD + k + 1]);
    }

    // ---- staging mapping: lane = (sc k-chunk, srg batch-group) ----
    const int sc = lane & 7, srg = lane >> 3;

    // ---- preload x[0] into this warp's xS slice ----
#pragma unroll
    for (int i = 0; i < 8; i++) {
        int b = srg + 4 * i;
        float4 v = __ldcg((const float4*)(x + (size_t)b * DD + w * KSL) + sc);
        *(float4*)&s->xS[b * HSTR + w * KSL + 4 * sc] = v;
    }

    // ---- reduce mapping: thread owns gate element (q, cc, bb) ----
    const int cc = w >> 2, bh8 = w & 3;
    const int q = lane >> 3, b8 = lane & 7;
    const int bb = bh8 * 8 + b8;
    const float bhb = b_ih[q * HH + j0 + cc] + b_hh[q * HH + j0 + cc];
    float cs = 0.f;
    if (q == 0) cs = c0[(size_t)bb * HH + j0 + cc];
    float h_keep = 0.f, c_keep = 0.f;
    __syncthreads();   // w2ih (+ own xS via warp order) visible

    for (int t = 0; t < TT; t++) {
        // ======== x-GEMM from xS (SMEM; same access pattern as h-GEMM) ======
        unsigned long long accA[8], accB[8];
#pragma unroll
        for (int j = 0; j < 8; j++) {
            const ulonglong2* xp =
                (const ulonglong2*)&s->xS[(4 * j + bq) * HSTR + w * KSL];
            unsigned long long a0 = 0ull, a1 = 0ull;
#pragma unroll
            for (int m = 0; m < 8; m++) {
                ulonglong2 xv = xp[m];               // k-pairs 2m, 2m+1
                ulonglong2 w0 = *(const ulonglong2*)&s->w2ih[w * 256 + (2 * m) * 16 + r0];
                ulonglong2 w1 = *(const ulonglong2*)&s->w2ih[w * 256 + (2 * m + 1) * 16 + r0];
                ffma2(a0, xv.x, w0.x);
                ffma2(a1, xv.x, w0.y);
                ffma2(a0, xv.y, w1.x);
                ffma2(a1, xv.y, w1.y);
            }
            accA[j] = a0; accB[j] = a1;
        }
        __syncwarp();   // all lanes done reading this warp's xS slice

        // ======== prefetch x[t+1] into own xS slice (latency hidden) ========
        if (t + 1 < TT) {
            const float* xn = x + (size_t)(t + 1) * BB * DD;
#pragma unroll
            for (int i = 0; i < 8; i++) {
                int b = srg + 4 * i;
                float4 v = __ldcg((const float4*)(xn + (size_t)b * DD + w * KSL) + sc);
                *(float4*)&s->xS[b * HSTR + w * KSL + 4 * sc] = v;
            }
        }

        // ======== per-warp producer wait (window {t, t+1}) ==================
        if (t > 0) {
            if (lane < 8) {
                const unsigned* fp = &g_flags[(w * 8 + lane) * 32];
                unsigned want = (unsigned)t, v;
                do {
                    asm volatile("ld.acquire.gpu.u32 %0, [%1];"
                                 : "=r"(v) : "l"(fp) : "memory");
                } while (v - want > 1u);
            }
            __syncwarp();
        }

        // ======== per-warp stage: own 32-k slice of h for all 32 batches ====
        const float* hsrc = (t == 0) ? h0 : g_hbuf[t & 1];   // [b][k]
#pragma unroll
        for (int i = 0; i < 8; i++) {
            int b = srg + 4 * i;
            float4 v = __ldcg((const float4*)(hsrc + (size_t)b * HH + w * KSL) + sc);
            *(float4*)&s->hS[b * HSTR + w * KSL + 4 * sc] = v;
        }
        __syncwarp();

        // ======== h-GEMM: acc += h · W_hh (weights in registers) ============
#pragma unroll
        for (int j = 0; j < 8; j++) {
            const ulonglong2* hp =
                (const ulonglong2*)&s->hS[(4 * j + bq) * HSTR + w * KSL];
            unsigned long long a0 = accA[j], a1 = accB[j];
#pragma unroll
            for (int m = 0; m < 8; m++) {
                ulonglong2 hv = hp[m];               // k-pairs 2m, 2m+1
                ffma2(a0, hv.x, wA[2 * m]);
                ffma2(a1, hv.x, wB[2 * m]);
                ffma2(a0, hv.y, wA[2 * m + 1]);
                ffma2(a1, hv.y, wB[2 * m + 1]);
            }
            accA[j] = a0; accB[j] = a1;
        }

        // ======== fold k-parity, publish partials ===========================
#pragma unroll
        for (int j = 0; j < 8; j++) {
            float lo, hi;
            upk2(accA[j], lo, hi);
            s->gred[w][r0][4 * j + bq] = lo + hi;
            upk2(accB[j], lo, hi);
            s->gred[w][r1][4 * j + bq] = lo + hi;
        }
        __syncthreads();

        // ======== distributed reduce + gates ================================
        float gate = bhb;
#pragma unroll
        for (int ww = 0; ww < NW; ww++)
            gate += s->gred[ww][q * 4 + cc][bb];
        float act = (q == 2) ? tanh_f(gate) : sigmoid_f(gate);
        float a1 = __shfl_xor_sync(0xffffffffu, act, 8);    // q^1
        float a2 = __shfl_xor_sync(0xffffffffu, act, 16);   // q^2
        float a3 = __shfl_xor_sync(0xffffffffu, a1, 16);    // q^3
        float hn = 0.f;
        if (q == 0) {
            float iv = act, fv = a1, gv = a2, ov = a3;
            float cn = fv * cs + iv * gv;
            hn = ov * tanh_f(cn);
            cs = cn;
            g_hbuf[(t + 1) & 1][(size_t)bb * HH + j0 + cc] = hn;
            h_keep = hn; c_keep = cn;
        }
        __syncthreads();   // all h writes + gred reads complete

        // ======== release own flag; out[t] store off the critical path ======
        if (tid == 0) {
            asm volatile("st.release.gpu.u32 [%0], %1;"
                         :: "l"(&g_flags[cid * 32]), "r"((unsigned)(t + 1))
                         : "memory");
        }
        if (q == 0)
            out[(size_t)t * BB * HH + (size_t)bb * HH + j0 + cc] = hn;
    }

    if (write_state && q == 0) {
        out[(size_t)TT * BB * HH + (size_t)bb * HH + j0 + cc] = h_keep;
        out[(size_t)TT * BB * HH + (size_t)BB * HH + (size_t)bb * HH + j0 + cc] = c_keep;
    }
}

// =====================================================================
// launch — single fused kernel, no pre-pass, no big scratch
// =====================================================================
extern "C" void kernel_launch(void* const* d_in, const int* in_sizes, int n_in,
                              void* d_out, int out_size) {
    const float* x    = (const float*)d_in[0];
    const float* h0   = (const float*)d_in[1];
    const float* c0   = (const float*)d_in[2];
    const float* w_ih = (const float*)d_in[3];
    const float* w_hh = (const float*)d_in[4];
    const float* b_ih = (const float*)d_in[5];
    const float* b_hh = (const float*)d_in[6];
    float* out = (float*)d_out;

    int smem = (int)sizeof(SmemR);
    cudaFuncSetAttribute(lstm_fused, cudaFuncAttributeMaxDynamicSharedMemorySize, smem);
    int write_state = (out_size >= TT * BB * HH + 2 * BB * HH) ? 1 : 0;
    lstm_fused<<<NCTA, RTHREADS, smem>>>(x, h0, c0, w_ih, w_hh, b_ih, b_hh,
                                         out, write_state);
}

// round 16
// speedup vs baseline: 2.1811x; 1.1663x over previous
#include <cuda_runtime.h>
#include <cstdint>
#include <math.h>

#define TT 2048
#define BB 32
#define DD 512
#define HH 512
#define GG 2048        // 4*H
#define NCTA 128       // 4 batch-groups x 32 cell-CTAs
#define RTHREADS 512   // 16 warps
#define NW 16
#define KSL 32         // k-slice per warp

// ---------------- device scratch (static, no allocs) ----------------
__device__ __align__(16) float g_pre[(size_t)TT * GG * BB];   // [t][gate_row][b]
__device__ __align__(16) float g_hbuf[2][4][8][HH];           // [par][group][b][cell]
__device__ __align__(128) unsigned g_flags[NCTA * 32];        // 1 flag/CTA, own 128B line

// ---------------- packed fp32x2 helpers ----------------
__device__ __forceinline__ unsigned long long pk2(float lo, float hi) {
    unsigned long long r;
    asm("mov.b64 %0, {%1, %2};" : "=l"(r) : "f"(lo), "f"(hi));
    return r;
}
__device__ __forceinline__ void upk2(unsigned long long v, float& lo, float& hi) {
    asm("mov.b64 {%0, %1}, %2;" : "=f"(lo), "=f"(hi) : "l"(v));
}
__device__ __forceinline__ void ffma2(unsigned long long& acc, unsigned long long a,
                                      unsigned long long b) {
    asm("fma.rn.f32x2 %0, %1, %2, %0;" : "+l"(acc) : "l"(a), "l"(b));
}
__device__ __forceinline__ float sigmoid_f(float x) {
    return __fdividef(1.f, 1.f + __expf(-x));
}
__device__ __forceinline__ float tanh_f(float x) {
    return 2.f * __fdividef(1.f, 1.f + __expf(-2.f * x)) - 1.f;
}

// =====================================================================
// Kernel A: pre[t][g][b] = sum_k x[t][b][k] * w_ih[g][k] + b_ih[g]
// (unchanged; ~3.4ms)
// =====================================================================
#define BM 128
#define BN 64
#define BK 16

__global__ __launch_bounds__(256) void pre_gemm(const float* __restrict__ x,
                                                const float* __restrict__ w,
                                                const float* __restrict__ bias) {
    __shared__ __align__(16) float As[BK][BM];
    __shared__ __align__(16) float Bs[BK][BN];

    const int m0 = blockIdx.y * BM;
    const int n0 = blockIdx.x * BN;
    const int tid = threadIdx.x;
    const int tx = tid & 15;
    const int ty = tid >> 4;

    unsigned long long acc[4][4];
#pragma unroll
    for (int i = 0; i < 4; i++)
#pragma unroll
        for (int j = 0; j < 4; j++) acc[i][j] = 0ull;

    for (int k0 = 0; k0 < DD; k0 += BK) {
#pragma unroll
        for (int l = 0; l < 2; l++) {
            int p = tid + l * 256;
            int row = p >> 2, kq = (p & 3) * 4;
            float4 v = *(const float4*)&x[(size_t)(m0 + row) * DD + k0 + kq];
            As[kq + 0][row] = v.x; As[kq + 1][row] = v.y;
            As[kq + 2][row] = v.z; As[kq + 3][row] = v.w;
        }
        {
            int row = tid >> 2, kq = (tid & 3) * 4;
            float4 v = *(const float4*)&w[(size_t)(n0 + row) * DD + k0 + kq];
            Bs[kq + 0][row] = v.x; Bs[kq + 1][row] = v.y;
            Bs[kq + 2][row] = v.z; Bs[kq + 3][row] = v.w;
        }
        __syncthreads();

#pragma unroll
        for (int k = 0; k < BK; k++) {
            float4 a01 = *(const float4*)&As[k][ty * 8];
            float4 a23 = *(const float4*)&As[k][ty * 8 + 4];
            float4 bf  = *(const float4*)&Bs[k][tx * 4];
            unsigned long long A[4] = { pk2(a01.x, a01.y), pk2(a01.z, a01.w),
                                        pk2(a23.x, a23.y), pk2(a23.z, a23.w) };
            unsigned long long Bv[4] = { pk2(bf.x, bf.x), pk2(bf.y, bf.y),
                                         pk2(bf.z, bf.z), pk2(bf.w, bf.w) };
#pragma unroll
            for (int i = 0; i < 4; i++)
#pragma unroll
                for (int j = 0; j < 4; j++) ffma2(acc[i][j], A[i], Bv[j]);
        }
        __syncthreads();
    }

#pragma unroll
    for (int j = 0; j < 4; j++) {
        int n = n0 + tx * 4 + j;
        float bsv = bias[n];
#pragma unroll
        for (int i = 0; i < 4; i++) {
            float lo, hi;
            upk2(acc[i][j], lo, hi);
            int m_lo = m0 + ty * 8 + i * 2;
            int t0 = m_lo >> 5, b_lo = m_lo & 31;
            g_pre[(size_t)t0 * GG * BB + (size_t)n * BB + b_lo] = lo + bsv;
            int m_hi = m_lo + 1;
            int t1 = m_hi >> 5, b_hi = m_hi & 31;
            g_pre[(size_t)t1 * GG * BB + (size_t)n * BB + b_hi] = hi + bsv;
        }
    }
}

// =====================================================================
// Kernel B: batch-grouped persistent recurrence.
//   CTA cid = g*32 + c: group g owns batches [8g,8g+8); CTA owns cells
//   [16c,16c+16) => 64 gate rows, CTA-local row r = 4*cell + q.
//   GEMM: warp w owns k in [32w,32w+32); lane owns rows 2lane, 2lane+1
//   for all 8 batches. W_hh: 32 persistent f32x2 regs/lane. h operands
//   broadcast from a 16KB hS. Reduce: thread owns (cell=warp, q, b);
//   gred[ww][r][8] is bank-perfect (bank = 8q+b). Sync: per-warp waits
//   on 2 producer CTAs within the group (window {t,t+1}).
// =====================================================================
struct __align__(16) SmemR {
    float hS[NW * 8 * KSL];      // [w][b][k] per-warp slices      16384 B
    float gred[NW][64][8];       // [ww][r=4*cell+q][b]            32768 B
};

__global__ __launch_bounds__(RTHREADS, 1) void lstm_recur(
    const float* __restrict__ h0, const float* __restrict__ c0,
    const float* __restrict__ w_hh, const float* __restrict__ b_hh,
    float* __restrict__ out, int write_state) {
    extern __shared__ char smem_raw[];
    SmemR* s = (SmemR*)smem_raw;

    const int tid = threadIdx.x;
    const int w = tid >> 5, lane = tid & 31;
    const int cid = blockIdx.x;
    const int g = cid >> 5, c = cid & 31;
    const int j0 = c * 16;          // first cell owned
    const int bg0 = g * 8;          // first batch owned

    // ---- GEMM rows: CTA-local r = 4*cell + q; lane owns r0, r1 ----
    const int r0 = 2 * lane, r1 = r0 + 1;
    const int R0 = (r0 & 3) * HH + j0 + (r0 >> 2);   // global gate row
    const int R1 = (r1 & 3) * HH + j0 + (r1 >> 2);

    // ---- persistent W_hh registers ----
    unsigned long long wA[16], wB[16];
#pragma unroll
    for (int m = 0; m < 8; m++) {
        float4 a = *(const float4*)&w_hh[(size_t)R0 * HH + w * KSL + 4 * m];
        wA[2 * m] = pk2(a.x, a.y); wA[2 * m + 1] = pk2(a.z, a.w);
        float4 b = *(const float4*)&w_hh[(size_t)R1 * HH + w * KSL + 4 * m];
        wB[2 * m] = pk2(b.x, b.y); wB[2 * m + 1] = pk2(b.z, b.w);
    }

    // ---- staging map: lane -> (b = lane>>3, kc = lane&7), 2 iters ----
    const int skc = lane & 7, sb = lane >> 3;

    // ---- reduce map: thread owns (cell = w, q = lane>>3, b = lane&7) ----
    const int q = lane >> 3, b8 = lane & 7;
    const int Rr = q * HH + j0 + w;          // global gate row of owned element
    const int bglob = bg0 + b8;              // global batch
    const float bhb = b_hh[Rr];
    float pq = g_pre[(size_t)Rr * BB + bglob];   // pre[0] (b_ih included)
    float cs = 0.f;
    if (q == 0) cs = c0[(size_t)bglob * HH + j0 + w];
    float h_keep = 0.f, c_keep = 0.f;

    for (int t = 0; t < TT; t++) {
        // ---- prefetch next pre value ----
        float pqn = 0.f;
        if (t + 1 < TT)
            pqn = __ldcg(&g_pre[(size_t)(t + 1) * GG * BB + (size_t)Rr * BB + bglob]);

        // ---- per-warp producer wait: cells [32w,32w+32) = CTAs 2w, 2w+1 ----
        if (t > 0) {
            if (lane < 2) {
                const unsigned* fp = &g_flags[(g * 32 + 2 * w + lane) * 32];
                unsigned want = (unsigned)t, v;
                do {
                    asm volatile("ld.acquire.gpu.u32 %0, [%1];"
                                 : "=r"(v) : "l"(fp) : "memory");
                } while (v - want > 1u);
            }
            __syncwarp();
        }

        // ---- stage own k-slice: 8 batches x 32 cells -> hS[w][b][k] ----
        const float* hbase = (t == 0) ? (h0 + (size_t)bg0 * HH)
                                      : &g_hbuf[t & 1][g][0][0];   // [b][cell]
#pragma unroll
        for (int i = 0; i < 2; i++) {
            int b = sb + 4 * i;
            float4 v = __ldcg((const float4*)(hbase + (size_t)b * HH + w * KSL) + skc);
            *(float4*)&s->hS[(w * 8 + b) * KSL + skc * 4] = v;
        }
        __syncwarp();

        // ---- GEMM: rows r0,r1 x 8 batches; h broadcast, W in regs ----
        unsigned long long accA[8], accB[8];
#pragma unroll
        for (int b = 0; b < 8; b++) {
            const ulonglong2* hp = (const ulonglong2*)&s->hS[(w * 8 + b) * KSL];
            unsigned long long a0 = 0ull, a1 = 0ull;
#pragma unroll
            for (int m = 0; m < 8; m++) {
                ulonglong2 hv = hp[m];               // k 4m..4m+3
                ffma2(a0, hv.x, wA[2 * m]);
                ffma2(a1, hv.x, wB[2 * m]);
                ffma2(a0, hv.y, wA[2 * m + 1]);
                ffma2(a1, hv.y, wB[2 * m + 1]);
            }
            accA[b] = a0; accB[b] = a1;
        }

        // ---- fold k-parity, publish 16 floats (rows r0,r1 x 8b) ----
        {
            float f0[8], f1[8];
#pragma unroll
            for (int b = 0; b < 8; b++) {
                float lo, hi;
                upk2(accA[b], lo, hi); f0[b] = lo + hi;
                upk2(accB[b], lo, hi); f1[b] = lo + hi;
            }
            float4* dst = (float4*)&s->gred[w][r0][0];   // 16 contiguous floats
            dst[0] = make_float4(f0[0], f0[1], f0[2], f0[3]);
            dst[1] = make_float4(f0[4], f0[5], f0[6], f0[7]);
            dst[2] = make_float4(f1[0], f1[1], f1[2], f1[3]);
            dst[3] = make_float4(f1[4], f1[5], f1[6], f1[7]);
        }
        __syncthreads();

        // ---- distributed reduce + gates: element (cell=w, q, b) ----
        float gate = pq + bhb;
#pragma unroll
        for (int ww = 0; ww < NW; ww++)
            gate += s->gred[ww][4 * w + q][b8];      // bank = 8q+b: perfect
        float act = (q == 2) ? tanh_f(gate) : sigmoid_f(gate);
        float a1 = __shfl_xor_sync(0xffffffffu, act, 8);    // q^1
        float a2 = __shfl_xor_sync(0xffffffffu, act, 16);   // q^2
        float a3 = __shfl_xor_sync(0xffffffffu, a1, 16);    // q^3
        float hn = 0.f;
        if (q == 0) {
            float iv = act, fv = a1, gv = a2, ov = a3;
            float cn = fv * cs + iv * gv;
            hn = ov * tanh_f(cn);
            cs = cn;
            g_hbuf[(t + 1) & 1][g][b8][j0 + w] = hn;
            h_keep = hn; c_keep = cn;
        }
        pq = pqn;
        __syncthreads();   // h writes + gred reads complete

        // ---- release own flag; out[t] store off the critical path ----
        if (tid == 0) {
            asm volatile("st.release.gpu.u32 [%0], %1;"
                         :: "l"(&g_flags[cid * 32]), "r"((unsigned)(t + 1))
                         : "memory");
        }
        if (q == 0)
            out[(size_t)t * BB * HH + (size_t)bglob * HH + j0 + w] = hn;
    }

    if (write_state && q == 0) {
        out[(size_t)TT * BB * HH + (size_t)bglob * HH + j0 + w] = h_keep;
        out[(size_t)TT * BB * HH + (size_t)BB * HH + (size_t)bglob * HH + j0 + w] = c_keep;
    }
}

// =====================================================================
// launch
// =====================================================================
extern "C" void kernel_launch(void* const* d_in, const int* in_sizes, int n_in,
                              void* d_out, int out_size) {
    const float* x    = (const float*)d_in[0];
    const float* h0   = (const float*)d_in[1];
    const float* c0   = (const float*)d_in[2];
    const float* w_ih = (const float*)d_in[3];
    const float* w_hh = (const float*)d_in[4];
    const float* b_ih = (const float*)d_in[5];
    const float* b_hh = (const float*)d_in[6];
    float* out = (float*)d_out;

    dim3 gridA(GG / BN, (TT * BB) / BM);
    pre_gemm<<<gridA, 256>>>(x, w_ih, b_ih);

    int smem = (int)sizeof(SmemR);
    cudaFuncSetAttribute(lstm_recur, cudaFuncAttributeMaxDynamicSharedMemorySize, smem);
    int write_state = (out_size >= TT * BB * HH + 2 * BB * HH) ? 1 : 0;
    lstm_recur<<<NCTA, RTHREADS, smem>>>(h0, c0, w_hh, b_hh, out, write_state);
}

// round 17
// speedup vs baseline: 2.3184x; 1.0629x over previous
#include <cuda_runtime.h>
#include <cstdint>
#include <math.h>

#define TT 2048
#define BB 32
#define DD 512
#define HH 512
#define GG 2048        // 4*H
#define NCTA 128       // 4 batch-groups x 32 cell-CTAs
#define RTHREADS 512   // 16 warps
#define NW 16
#define KSL 32         // k-slice per warp

// ---------------- device scratch (static, no allocs) ----------------
__device__ __align__(16) float g_pre[(size_t)TT * GG * BB];   // [t][gate_row][b]
__device__ __align__(16) float g_hbuf[3][4][8][HH];           // depth-3 ring [slot][group][b][cell]
__device__ __align__(128) unsigned g_cellflag[4 * 512 * 32];  // 1 flag per (group, cell), own 128B line

// ---------------- packed fp32x2 helpers ----------------
__device__ __forceinline__ unsigned long long pk2(float lo, float hi) {
    unsigned long long r;
    asm("mov.b64 %0, {%1, %2};" : "=l"(r) : "f"(lo), "f"(hi));
    return r;
}
__device__ __forceinline__ void upk2(unsigned long long v, float& lo, float& hi) {
    asm("mov.b64 {%0, %1}, %2;" : "=f"(lo), "=f"(hi) : "l"(v));
}
__device__ __forceinline__ void ffma2(unsigned long long& acc, unsigned long long a,
                                      unsigned long long b) {
    asm("fma.rn.f32x2 %0, %1, %2, %0;" : "+l"(acc) : "l"(a), "l"(b));
}
__device__ __forceinline__ float sigmoid_f(float x) {
    return __fdividef(1.f, 1.f + __expf(-x));
}
__device__ __forceinline__ float tanh_f(float x) {
    return 2.f * __fdividef(1.f, 1.f + __expf(-2.f * x)) - 1.f;
}

// =====================================================================
// Kernel A: pre[t][g][b] = sum_k x[t][b][k] * w_ih[g][k] + b_ih[g]
// (unchanged; ~3.4ms)
// =====================================================================
#define BM 128
#define BN 64
#define BK 16

__global__ __launch_bounds__(256) void pre_gemm(const float* __restrict__ x,
                                                const float* __restrict__ w,
                                                const float* __restrict__ bias) {
    __shared__ __align__(16) float As[BK][BM];
    __shared__ __align__(16) float Bs[BK][BN];

    const int m0 = blockIdx.y * BM;
    const int n0 = blockIdx.x * BN;
    const int tid = threadIdx.x;
    const int tx = tid & 15;
    const int ty = tid >> 4;

    unsigned long long acc[4][4];
#pragma unroll
    for (int i = 0; i < 4; i++)
#pragma unroll
        for (int j = 0; j < 4; j++) acc[i][j] = 0ull;

    for (int k0 = 0; k0 < DD; k0 += BK) {
#pragma unroll
        for (int l = 0; l < 2; l++) {
            int p = tid + l * 256;
            int row = p >> 2, kq = (p & 3) * 4;
            float4 v = *(const float4*)&x[(size_t)(m0 + row) * DD + k0 + kq];
            As[kq + 0][row] = v.x; As[kq + 1][row] = v.y;
            As[kq + 2][row] = v.z; As[kq + 3][row] = v.w;
        }
        {
            int row = tid >> 2, kq = (tid & 3) * 4;
            float4 v = *(const float4*)&w[(size_t)(n0 + row) * DD + k0 + kq];
            Bs[kq + 0][row] = v.x; Bs[kq + 1][row] = v.y;
            Bs[kq + 2][row] = v.z; Bs[kq + 3][row] = v.w;
        }
        __syncthreads();

#pragma unroll
        for (int k = 0; k < BK; k++) {
            float4 a01 = *(const float4*)&As[k][ty * 8];
            float4 a23 = *(const float4*)&As[k][ty * 8 + 4];
            float4 bf  = *(const float4*)&Bs[k][tx * 4];
            unsigned long long A[4] = { pk2(a01.x, a01.y), pk2(a01.z, a01.w),
                                        pk2(a23.x, a23.y), pk2(a23.z, a23.w) };
            unsigned long long Bv[4] = { pk2(bf.x, bf.x), pk2(bf.y, bf.y),
                                         pk2(bf.z, bf.z), pk2(bf.w, bf.w) };
#pragma unroll
            for (int i = 0; i < 4; i++)
#pragma unroll
                for (int j = 0; j < 4; j++) ffma2(acc[i][j], A[i], Bv[j]);
        }
        __syncthreads();
    }

#pragma unroll
    for (int j = 0; j < 4; j++) {
        int n = n0 + tx * 4 + j;
        float bsv = bias[n];
#pragma unroll
        for (int i = 0; i < 4; i++) {
            float lo, hi;
            upk2(acc[i][j], lo, hi);
            int m_lo = m0 + ty * 8 + i * 2;
            int t0 = m_lo >> 5, b_lo = m_lo & 31;
            g_pre[(size_t)t0 * GG * BB + (size_t)n * BB + b_lo] = lo + bsv;
            int m_hi = m_lo + 1;
            int t1 = m_hi >> 5, b_hi = m_hi & 31;
            g_pre[(size_t)t1 * GG * BB + (size_t)n * BB + b_hi] = hi + bsv;
        }
    }
}

// =====================================================================
// Kernel B: batch-grouped persistent recurrence, PER-CELL flags.
//   CTA (g,c): group g owns batches [8g,8g+8); CTA owns cells
//   [16c,16c+16). Warp w owns cell 16c+w for the reduce AND k-slice
//   [32w,32w+32) for the GEMM. W_hh in 64 persistent regs/lane.
//   Warp releases its cell flag immediately after its 8 h-stores
//   (no CTA convergence on the release path). Depth-3 h ring +
//   window-2 polls (max spread 2, proven via 2-hop coupling).
//   gred parity-double-buffered -> only ONE syncthreads per step.
// =====================================================================
struct __align__(16) SmemR {
    float hS[NW * 8 * KSL];        // [w][b][k] per-warp slices     16384 B
    float gred[2][NW][64][8];      // [par][ww][r=4*cell+q][b]      65536 B
};

__global__ __launch_bounds__(RTHREADS, 1) void lstm_recur(
    const float* __restrict__ h0, const float* __restrict__ c0,
    const float* __restrict__ w_hh, const float* __restrict__ b_hh,
    float* __restrict__ out, int write_state) {
    extern __shared__ char smem_raw[];
    SmemR* s = (SmemR*)smem_raw;

    const int tid = threadIdx.x;
    const int w = tid >> 5, lane = tid & 31;
    const int cid = blockIdx.x;
    const int g = cid >> 5, c = cid & 31;
    const int j0 = c * 16;          // first cell owned
    const int bg0 = g * 8;          // first batch owned

    // ---- GEMM rows: CTA-local r = 4*cell + q; lane owns r0, r1 ----
    const int r0 = 2 * lane, r1 = r0 + 1;
    const int R0 = (r0 & 3) * HH + j0 + (r0 >> 2);   // global gate row
    const int R1 = (r1 & 3) * HH + j0 + (r1 >> 2);

    // ---- persistent W_hh registers ----
    unsigned long long wA[16], wB[16];
#pragma unroll
    for (int m = 0; m < 8; m++) {
        float4 a = *(const float4*)&w_hh[(size_t)R0 * HH + w * KSL + 4 * m];
        wA[2 * m] = pk2(a.x, a.y); wA[2 * m + 1] = pk2(a.z, a.w);
        float4 b = *(const float4*)&w_hh[(size_t)R1 * HH + w * KSL + 4 * m];
        wB[2 * m] = pk2(b.x, b.y); wB[2 * m + 1] = pk2(b.z, b.w);
    }

    // ---- staging map: lane -> (b = lane>>3, kc = lane&7), 2 iters ----
    const int skc = lane & 7, sb = lane >> 3;

    // ---- reduce map: thread owns (cell = w, q = lane>>3, b = lane&7) ----
    const int q = lane >> 3, b8 = lane & 7;
    const int Rr = q * HH + j0 + w;          // global gate row of owned element
    const int bglob = bg0 + b8;              // global batch
    const float bhb = b_hh[Rr];
    float pq = g_pre[(size_t)Rr * BB + bglob];   // pre[0] (b_ih included)
    float cs = 0.f;
    if (q == 0) cs = c0[(size_t)bglob * HH + j0 + w];
    float h_keep = 0.f, c_keep = 0.f;

    // per-warp flag addresses
    unsigned* my_flag = &g_cellflag[(g * 512 + j0 + w) * 32];          // owned cell
    const unsigned* poll_flag = &g_cellflag[(g * 512 + 32 * w + lane) * 32]; // lane's producer cell

    for (int t = 0; t < TT; t++) {
        const int par = t & 1;
        const int rslot = t % 3;
        const int wslot = (rslot == 2) ? 0 : rslot + 1;

        // ---- prefetch next pre value ----
        float pqn = 0.f;
        if (t + 1 < TT)
            pqn = __ldcg(&g_pre[(size_t)(t + 1) * GG * BB + (size_t)Rr * BB + bglob]);

        // ---- per-lane producer wait: lane l polls cell 32w+l (window 2) ----
        if (t > 0) {
            unsigned want = (unsigned)t, v;
            do {
                asm volatile("ld.acquire.gpu.u32 %0, [%1];"
                             : "=r"(v) : "l"(poll_flag) : "memory");
            } while (v - want > 2u);   // pass on v in {t, t+1, t+2}
            __syncwarp();
        }

        // ---- stage own k-slice: 8 batches x 32 cells -> hS[w][b][k] ----
        const float* hbase = (t == 0) ? (h0 + (size_t)bg0 * HH)
                                      : &g_hbuf[rslot][g][0][0];   // [b][cell]
#pragma unroll
        for (int i = 0; i < 2; i++) {
            int b = sb + 4 * i;
            float4 v = __ldcg((const float4*)(hbase + (size_t)b * HH + w * KSL) + skc);
            *(float4*)&s->hS[(w * 8 + b) * KSL + skc * 4] = v;
        }
        __syncwarp();

        // ---- GEMM: rows r0,r1 x 8 batches; h broadcast, W in regs ----
        unsigned long long accA[8], accB[8];
#pragma unroll
        for (int b = 0; b < 8; b++) {
            const ulonglong2* hp = (const ulonglong2*)&s->hS[(w * 8 + b) * KSL];
            unsigned long long a0 = 0ull, a1 = 0ull;
#pragma unroll
            for (int m = 0; m < 8; m++) {
                ulonglong2 hv = hp[m];               // k 4m..4m+3
                ffma2(a0, hv.x, wA[2 * m]);
                ffma2(a1, hv.x, wB[2 * m]);
                ffma2(a0, hv.y, wA[2 * m + 1]);
                ffma2(a1, hv.y, wB[2 * m + 1]);
            }
            accA[b] = a0; accB[b] = a1;
        }

        // ---- fold k-parity, publish 16 floats into gred[par] ----
        {
            float f0[8], f1[8];
#pragma unroll
            for (int b = 0; b < 8; b++) {
                float lo, hi;
                upk2(accA[b], lo, hi); f0[b] = lo + hi;
                upk2(accB[b], lo, hi); f1[b] = lo + hi;
            }
            float4* dst = (float4*)&s->gred[par][w][r0][0];
            dst[0] = make_float4(f0[0], f0[1], f0[2], f0[3]);
            dst[1] = make_float4(f0[4], f0[5], f0[6], f0[7]);
            dst[2] = make_float4(f1[0], f1[1], f1[2], f1[3]);
            dst[3] = make_float4(f1[4], f1[5], f1[6], f1[7]);
        }
        __syncthreads();   // the ONLY CTA-wide barrier per step

        // ---- distributed reduce + gates: element (cell=w, q, b) ----
        float gate = pq + bhb;
#pragma unroll
        for (int ww = 0; ww < NW; ww++)
            gate += s->gred[par][ww][4 * w + q][b8];   // bank = 8q+b: perfect
        float act = (q == 2) ? tanh_f(gate) : sigmoid_f(gate);
        float a1 = __shfl_xor_sync(0xffffffffu, act, 8);    // q^1
        float a2 = __shfl_xor_sync(0xffffffffu, act, 16);   // q^2
        float a3 = __shfl_xor_sync(0xffffffffu, a1, 16);    // q^3
        float hn = 0.f;
        if (q == 0) {
            float iv = act, fv = a1, gv = a2, ov = a3;
            float cn = fv * cs + iv * gv;
            hn = ov * tanh_f(cn);
            cs = cn;
            g_hbuf[wslot][g][b8][j0 + w] = hn;   // h(t+1) into depth-3 ring
            h_keep = hn; c_keep = cn;
        }
        pq = pqn;
        __syncwarp();      // warp's 8 h-stores ordered before its release

        // ---- per-warp EARLY release of this cell's flag ----
        if (lane == 0) {
            asm volatile("st.release.gpu.u32 [%0], %1;"
                         :: "l"(my_flag), "r"((unsigned)(t + 1)) : "memory");
        }
        // out[t] store off the critical path
        if (q == 0)
            out[(size_t)t * BB * HH + (size_t)bglob * HH + j0 + w] = hn;
    }

    if (write_state && q == 0) {
        out[(size_t)TT * BB * HH + (size_t)bglob * HH + j0 + w] = h_keep;
        out[(size_t)TT * BB * HH + (size_t)BB * HH + (size_t)bglob * HH + j0 + w] = c_keep;
    }
}

// =====================================================================
// launch
// =====================================================================
extern "C" void kernel_launch(void* const* d_in, const int* in_sizes, int n_in,
                              void* d_out, int out_size) {
    const float* x    = (const float*)d_in[0];
    const float* h0   = (const float*)d_in[1];
    const float* c0   = (const float*)d_in[2];
    const float* w_ih = (const float*)d_in[3];
    const float* w_hh = (const float*)d_in[4];
    const float* b_ih = (const float*)d_in[5];
    const float* b_hh = (const float*)d_in[6];
    float* out = (float*)d_out;

    dim3 gridA(GG / BN, (TT * BB) / BM);
    pre_gemm<<<gridA, 256>>>(x, w_ih, b_ih);

    int smem = (int)sizeof(SmemR);
    cudaFuncSetAttribute(lstm_recur, cudaFuncAttributeMaxDynamicSharedMemorySize, smem);
    int write_state = (out_size >= TT * BB * HH + 2 * BB * HH) ? 1 : 0;
    lstm_recur<<<NCTA, RTHREADS, smem>>>(h0, c0, w_hh, b_hh, out, write_state);
}